// round 17
// baseline (speedup 1.0000x reference)
#include <cuda_runtime.h>
#include <math.h>

// GibbsSampler — round 17: single-barrier epoch waves (sweep 1) +
// wave-compacted replay (sweep 2).
//
// Sweep 1: per 1024-chunk, deps = neighbor cells with posG in
// [chunk_base, my_pos). done[tid] stores the GLOBAL wave counter at
// execution; readiness = all deps have wbase < done < wcnt (finished in an
// earlier wave of this chunk) => check and execute merged, ONE barrier per
// wave, no done resets. At chunk end, positions are counting-sorted by wave
// into global (site, r2, wave) arrays.
// Sweep 2: replays the recorded waves with contiguous (warp-coherent) active
// slots; one barrier per wave. Conflicting pairs have strictly increasing
// waves; same-wave updates are pairwise non-conflicting => race-free.
//
// Numerics: bit-exact pipeline from rounds 7-16 (double-precision exp table,
// _rn mul/sub/add/div, sequential cumsum). OUTPUT IS FLOAT32.

#define NSITES 65536
#define BLOCK   1024
#define NCHUNK  64
#define LCAP    32     // max per-chunk wave depth tracked (P(depth>31) ~ 0)

__device__ unsigned short g_ssite[NSITES];  // wave-sorted site per chunk
__device__ float          g_sr2[NSITES];    // wave-sorted sweep-2 uniform
__device__ unsigned char  g_swave[NSITES];  // wave index per sorted slot

__global__ __launch_bounds__(BLOCK, 1)
void gibbs_r17(const unsigned int* __restrict__ A,   // X_init or perm
               const unsigned int* __restrict__ B,   // the other one
               const float* __restrict__ U,          // uniforms (2,65536)
               const unsigned int* __restrict__ s0,  // beta or K
               const unsigned int* __restrict__ s1,  // the other one
               float* __restrict__ out)              // FLOAT32 output
{
    extern __shared__ unsigned char dyn[];
    unsigned short* posG = (unsigned short*)dyn;      // [0,131072): cell -> position
    unsigned char*  Xs   = dyn + 131072;              // [131072,196608): lattice

    __shared__ float4         s_B[729];
    __shared__ unsigned short s_done[BLOCK];          // global wave at execution
    __shared__ int            s_cmax[NCHUNK];
    __shared__ int            s_lh[LCAP + 1];         // per-chunk wave histogram
    __shared__ int            s_ls[LCAP + 1];         // wave start offsets
    __shared__ int            s_lo[LCAP + 1];         // scatter cursors
    __shared__ unsigned int   s_maxA, s_maxB;

    const int tid  = threadIdx.x;
    const int lane = tid & 31;

    // ---------- classification: 1024-sample (provably sufficient) ----------
    // any 1024 DISTINCT values from 0..65535 contain at most four <= 3 =>
    // perm always shows a value > 3 in the first 1024; X_init never does.
    if (tid == 0) { s_maxA = 0u; s_maxB = 0u; }
    if (tid < NCHUNK) s_cmax[tid] = 0;
    s_done[tid] = 0;
    __syncthreads();
    atomicMax(&s_maxA, __ldg(&A[tid]));
    atomicMax(&s_maxB, __ldg(&B[tid]));

    const unsigned int w0 = __ldg(s0);
    const unsigned int w1 = __ldg(s1);
    float beta;
    if (w0 == 4u)      beta = __uint_as_float(w1);
    else if (w1 == 4u) beta = __uint_as_float(w0);
    else if (w0 >= 0x3F000000u && w0 < 0x3FC00000u) beta = __uint_as_float(w0);
    else               beta = __uint_as_float(w1);
    __syncthreads();
    const int b_is_x = (s_maxB <= 3u) && (s_maxA > 3u);
    const unsigned int* Xw = b_is_x ? B : A;
    const unsigned int* Pw = b_is_x ? A : B;

    // ---------- boundary table (bit-exact) ----------
    for (int t = tid; t < 729; t += BLOCK) {
        int c0 = t % 9, c1 = (t / 9) % 9, c2 = t / 81;
        int c3 = 8 - c0 - c1 - c2;
        if (c3 >= 0) {
            int cm = max(max(c0, c1), max(c2, c3));
            float bm = __fmul_rn(beta, (float)cm);
            float e0 = (float)exp((double)__fsub_rn(__fmul_rn(beta, (float)c0), bm));
            float e1 = (float)exp((double)__fsub_rn(__fmul_rn(beta, (float)c1), bm));
            float e2 = (float)exp((double)__fsub_rn(__fmul_rn(beta, (float)c2), bm));
            float e3 = (float)exp((double)__fsub_rn(__fmul_rn(beta, (float)c3), bm));
            float s  = __fadd_rn(__fadd_rn(__fadd_rn(e0, e1), e2), e3);
            float a0 = __fdiv_rn(e0, s);
            float a1 = __fadd_rn(a0, __fdiv_rn(e1, s));
            float a2 = __fadd_rn(a1, __fdiv_rn(e2, s));
            float a3 = __fadd_rn(a2, __fdiv_rn(e3, s));
            s_B[t] = make_float4(a0, a1, a2, a3);
        }
    }

    // ---------- posG (inverse perm) + lattice ----------
    for (int p = tid; p < NSITES; p += BLOCK)
        posG[(int)__ldg(&Pw[p])] = (unsigned short)p;
    for (int i = tid; i < NSITES; i += BLOCK)
        Xs[i] = (unsigned char)(__ldg(&Xw[i]) & 3u);
    __syncthreads();

    // ================= SWEEP 1: single-barrier waves + sort =================
    int wcnt = 0;   // global wave counter (lockstep across threads)
    for (int chunk = 0; chunk < NCHUNK; chunk++) {
        const int base = chunk << 10;
        const int idx  = base + tid;
        const int site = (int)__ldg(&Pw[idx]);
        const float r  = __ldg(&U[idx]);
        const float r2 = __ldg(&U[NSITES + idx]);
        const int u = site >> 8, v = site & 255;
        const int um = (u > 0)   ? u - 1 : 0;
        const int up = (u < 255) ? u + 1 : 255;
        const int vm = (v > 0)   ? v - 1 : 0;
        const int vp = (v < 255) ? v + 1 : 255;
        const int ra = um << 8, rb = u << 8, rc = up << 8;
        const int na0 = ra | vm, na1 = ra | v, na2 = ra | vp;
        const int na3 = rb | vm,               na4 = rb | vp;
        const int na5 = rc | vm, na6 = rc | v, na7 = rc | vp;

        // deps: in-chunk earlier positions in my clipped 3x3 box
        // (own cell reads posG == idx -> excluded; clip-dups likewise)
        int sp0, sp1, sp2, sp3, sp4, sp5, sp6, sp7, p;
        p = (int)posG[na0]; sp0 = (p >= base && p < idx) ? (p - base) : -1;
        p = (int)posG[na1]; sp1 = (p >= base && p < idx) ? (p - base) : -1;
        p = (int)posG[na2]; sp2 = (p >= base && p < idx) ? (p - base) : -1;
        p = (int)posG[na3]; sp3 = (p >= base && p < idx) ? (p - base) : -1;
        p = (int)posG[na4]; sp4 = (p >= base && p < idx) ? (p - base) : -1;
        p = (int)posG[na5]; sp5 = (p >= base && p < idx) ? (p - base) : -1;
        p = (int)posG[na6]; sp6 = (p >= base && p < idx) ? (p - base) : -1;
        p = (int)posG[na7]; sp7 = (p >= base && p < idx) ? (p - base) : -1;

        // clear sort state for this chunk
        if (tid <= LCAP) s_lh[tid] = 0;
        const int wbase = wcnt;
        __syncthreads();   // prior chunk committed; s_lh reset visible

        int mydone = 0, myl = 0;
        for (;;) {
            wcnt++;
            if (!mydone) {
                int ready = 1, dv;
                if (sp0 >= 0) { dv = (int)s_done[sp0]; ready &= (dv > wbase) & (dv < wcnt); }
                if (sp1 >= 0) { dv = (int)s_done[sp1]; ready &= (dv > wbase) & (dv < wcnt); }
                if (sp2 >= 0) { dv = (int)s_done[sp2]; ready &= (dv > wbase) & (dv < wcnt); }
                if (sp3 >= 0) { dv = (int)s_done[sp3]; ready &= (dv > wbase) & (dv < wcnt); }
                if (sp4 >= 0) { dv = (int)s_done[sp4]; ready &= (dv > wbase) & (dv < wcnt); }
                if (sp5 >= 0) { dv = (int)s_done[sp5]; ready &= (dv > wbase) & (dv < wcnt); }
                if (sp6 >= 0) { dv = (int)s_done[sp6]; ready &= (dv > wbase) & (dv < wcnt); }
                if (sp7 >= 0) { dv = (int)s_done[sp7]; ready &= (dv > wbase) & (dv < wcnt); }
                if (ready) {
                    unsigned int acc = 0u;   // byte-packed counts of classes 0-2
                    acc += 1u << (((unsigned)Xs[na0]) * 8u);
                    acc += 1u << (((unsigned)Xs[na1]) * 8u);
                    acc += 1u << (((unsigned)Xs[na2]) * 8u);
                    acc += 1u << (((unsigned)Xs[na3]) * 8u);
                    acc += 1u << (((unsigned)Xs[na4]) * 8u);
                    acc += 1u << (((unsigned)Xs[na5]) * 8u);
                    acc += 1u << (((unsigned)Xs[na6]) * 8u);
                    acc += 1u << (((unsigned)Xs[na7]) * 8u);
                    int c0 = (int)(acc & 0xFFu);
                    int c1 = (int)((acc >> 8) & 0xFFu);
                    int c2 = (int)((acc >> 16) & 0xFFu);
                    float4 b = s_B[c0 + 9 * c1 + 81 * c2];
                    int x = (b.x < r) + (b.y < r) + (b.z < r) + (b.w < r);
                    Xs[site] = (unsigned char)x;
                    s_done[tid] = (unsigned short)wcnt;
                    mydone = 1;
                    myl = wcnt - wbase;
                }
            }
            if (__syncthreads_count(!mydone) == 0) break;
        }

        // ---- per-chunk counting sort by wave (for sweep 2) ----
        const int ml = min(myl, LCAP - 1);
        {
            unsigned m = __match_any_sync(0xFFFFFFFFu, ml);
            if ((int)(__ffs(m) - 1) == lane) atomicAdd(&s_lh[ml], __popc(m));
        }
        __syncthreads();
        if (tid == 0) {
            int acc = 0;
            for (int w = 1; w < LCAP; w++) { s_ls[w] = acc; s_lo[w] = acc; acc += s_lh[w]; }
            s_cmax[chunk] = 0;   // recomputed below via max level present
            for (int w = LCAP - 1; w >= 1; w--) if (s_lh[w]) { s_cmax[chunk] = w; break; }
        }
        __syncthreads();
        {
            unsigned m = __match_any_sync(0xFFFFFFFFu, ml);
            const int leader = __ffs(m) - 1;
            const int rank   = __popc(m & ((1u << lane) - 1u));
            int bslot = 0;
            if (lane == leader) bslot = atomicAdd(&s_lo[ml], __popc(m));
            bslot = __shfl_sync(0xFFFFFFFFu, bslot, leader);
            const int slot = base + bslot + rank;
            g_ssite[slot] = (unsigned short)site;
            g_sr2[slot]   = r2;
            g_swave[slot] = (unsigned char)ml;
        }
        // next chunk's first __syncthreads orders these writes (global mem:
        // consumed only in sweep 2, after more barriers)
    }
    __syncthreads();

    // ================= SWEEP 2: wave-compacted replay =================
    for (int chunk = 0; chunk < NCHUNK; chunk++) {
        const int base = chunk << 10;
        const int slot = base + tid;
        const int site = (int)__ldg(&g_ssite[slot]);
        const float r  = __ldg(&g_sr2[slot]);
        const int  myw = (int)__ldg(&g_swave[slot]);
        const int cmax = s_cmax[chunk];
        const int u = site >> 8, v = site & 255;
        const int um = (u > 0)   ? u - 1 : 0;
        const int up = (u < 255) ? u + 1 : 255;
        const int vm = (v > 0)   ? v - 1 : 0;
        const int vp = (v < 255) ? v + 1 : 255;
        const int ra = um << 8, rb = u << 8, rc = up << 8;

        for (int w = 1; w <= cmax; w++) {
            if (myw == w) {
                unsigned int acc = 0u;
                acc += 1u << (((unsigned)Xs[ra | vm]) * 8u);
                acc += 1u << (((unsigned)Xs[ra | v ]) * 8u);
                acc += 1u << (((unsigned)Xs[ra | vp]) * 8u);
                acc += 1u << (((unsigned)Xs[rb | vm]) * 8u);
                acc += 1u << (((unsigned)Xs[rb | vp]) * 8u);
                acc += 1u << (((unsigned)Xs[rc | vm]) * 8u);
                acc += 1u << (((unsigned)Xs[rc | v ]) * 8u);
                acc += 1u << (((unsigned)Xs[rc | vp]) * 8u);
                int c0 = (int)(acc & 0xFFu);
                int c1 = (int)((acc >> 8) & 0xFFu);
                int c2 = (int)((acc >> 16) & 0xFFu);
                float4 b = s_B[c0 + 9 * c1 + 81 * c2];
                int x = (b.x < r) + (b.y < r) + (b.z < r) + (b.w < r);
                Xs[site] = (unsigned char)x;
            }
            __syncthreads();   // wave w writes before wave w+1 reads
        }
    }

    // ---------- FLOAT32 output ----------
    for (int i = tid; i < NSITES; i += BLOCK)
        out[i] = (float)Xs[i];
}

extern "C" void kernel_launch(void* const* d_in, const int* in_sizes, int n_in,
                              void* d_out, int out_size)
{
    // element-count mapping: 131072 -> uniforms; 65536 x2 -> X_init/perm; 1 -> scalars
    const void* arr64k[2] = {0, 0}; int n64k = 0;
    const void* scal[2]   = {0, 0}; int nsc = 0;
    const void* unif = 0;
    for (int i = 0; i < n_in; i++) {
        int s = in_sizes[i];
        if (s == 131072) unif = d_in[i];
        else if (s == 65536) { if (n64k < 2) arr64k[n64k++] = d_in[i]; }
        else if (s == 1)     { if (nsc  < 2) scal[nsc++]   = d_in[i]; }
    }
    if (!unif || n64k < 2 || nsc < 1) {
        // positional fallback: X_init, perm, uniforms, beta, K
        arr64k[0] = d_in[0];
        arr64k[1] = (n_in > 1) ? d_in[1] : d_in[0];
        unif      = (n_in > 2) ? d_in[2] : d_in[0];
        scal[0]   = (n_in > 3) ? d_in[3] : d_in[0];
        scal[1]   = (n_in > 4) ? d_in[4] : scal[0];
    }
    if (!scal[1]) scal[1] = scal[0];

    const size_t dyn_bytes = 131072 + 65536;   // posG + Xs
    cudaFuncSetAttribute(gibbs_r17,
                         cudaFuncAttributeMaxDynamicSharedMemorySize,
                         (int)dyn_bytes);
    gibbs_r17<<<1, BLOCK, dyn_bytes>>>((const unsigned int*)arr64k[0],
                                       (const unsigned int*)arr64k[1],
                                       (const float*)unif,
                                       (const unsigned int*)scal[0],
                                       (const unsigned int*)scal[1],
                                       (float*)d_out);
}